// round 3
// baseline (speedup 1.0000x reference)
#include <cuda_runtime.h>
#include <cstdint>

#define BATCH 16
#define TLEN  256
#define HID   1024
#define EMB   512
#define VOC   32000
#define GATES 3072          // 3*HID
#define ROWS  4096          // BATCH*TLEN

// ---------------- device scratch (no allocations allowed) ----------------
__device__ float g_xW[ROWS * GATES];   // 50.3 MB: x@Wi + bi
__device__ float g_hs[ROWS * HID];     // 16.8 MB: all hidden states [B,T,H]
__device__ float g_h[2][BATCH * HID];  // double-buffered current h
__device__ unsigned g_bar_count = 0;
__device__ volatile unsigned g_bar_release = 0;  // monotonic epoch, survives replays

// ---------------- tf32 helpers ----------------
__device__ __forceinline__ unsigned f2tf32(float f) {
    unsigned u;
    asm("cvt.rna.tf32.f32 %0, %1;" : "=r"(u) : "f"(f));
    return u;
}

__device__ __forceinline__ void mma_tf32(float c[4], const unsigned a[4], const unsigned b[2]) {
    asm volatile(
        "mma.sync.aligned.m16n8k8.row.col.f32.tf32.tf32.f32 "
        "{%0,%1,%2,%3}, {%4,%5,%6,%7}, {%8,%9}, {%0,%1,%2,%3};"
        : "+f"(c[0]), "+f"(c[1]), "+f"(c[2]), "+f"(c[3])
        : "r"(a[0]), "r"(a[1]), "r"(a[2]), "r"(a[3]), "r"(b[0]), "r"(b[1]));
}

// ---------------------------------------------------------------------------
// Generic tf32 GEMM:  C[M,N] = A[M,K] @ B[K,N] + bias   (M = gridDim.y*128)
// A row-major with leading dim lda; optional row indirection Aidx (embedding
// gather fused into the A-tile load). All of M,N,K are multiples of the tile.
// Block tile 128x128x32, 8 warps (2x4), warp tile 64x32, mma m16n8k8.
// ---------------------------------------------------------------------------
__global__ __launch_bounds__(256) void gemm_tf32(
    const float* __restrict__ A, const int* __restrict__ Aidx,
    const float* __restrict__ B, const float* __restrict__ bias,
    float* __restrict__ C, int N, int K, int lda)
{
    __shared__ unsigned As[128 * 36];   // pad 36 -> conflict-free frag loads
    __shared__ unsigned Bs[32 * 132];   // pad 132

    const int t  = threadIdx.x;
    const int m0 = blockIdx.y * 128;
    const int n0 = blockIdx.x * 128;

    const int warp = t >> 5;
    const int lane = t & 31;
    const int gid  = lane >> 2;   // 0..7
    const int tig  = lane & 3;    // 0..3
    const int wm   = (warp >> 2) * 64;   // 0 or 64
    const int wn   = (warp & 3) * 32;    // 0,32,64,96

    float acc[4][4][4];
#pragma unroll
    for (int mf = 0; mf < 4; mf++)
#pragma unroll
        for (int nf = 0; nf < 4; nf++)
#pragma unroll
            for (int i = 0; i < 4; i++) acc[mf][nf][i] = 0.f;

    const int ar  = t >> 3;        // A tile row base (0..31)
    const int ac  = (t & 7) * 4;   // A tile col (0..28)
    const int bkr = t >> 5;        // B tile row base (0..7)
    const int bc  = (t & 31) * 4;  // B tile col (0..124)

    for (int k0 = 0; k0 < K; k0 += 32) {
        // ---- load A tile (with optional gather) ----
#pragma unroll
        for (int p = 0; p < 4; p++) {
            int r = ar + 32 * p;
            int grow = m0 + r;
            int arow = Aidx ? Aidx[grow] : grow;
            float4 v = *reinterpret_cast<const float4*>(A + (size_t)arow * lda + k0 + ac);
            unsigned* dst = &As[r * 36 + ac];
            dst[0] = f2tf32(v.x); dst[1] = f2tf32(v.y);
            dst[2] = f2tf32(v.z); dst[3] = f2tf32(v.w);
        }
        // ---- load B tile ----
#pragma unroll
        for (int p = 0; p < 4; p++) {
            int kr = bkr + 8 * p;
            float4 v = *reinterpret_cast<const float4*>(B + (size_t)(k0 + kr) * N + n0 + bc);
            unsigned* dst = &Bs[kr * 132 + bc];
            dst[0] = f2tf32(v.x); dst[1] = f2tf32(v.y);
            dst[2] = f2tf32(v.z); dst[3] = f2tf32(v.w);
        }
        __syncthreads();

#pragma unroll
        for (int ks = 0; ks < 4; ks++) {
            const int kk = ks * 8;
            unsigned af[4][4], bf[4][2];
#pragma unroll
            for (int mf = 0; mf < 4; mf++) {
                int r = wm + mf * 16 + gid;
                af[mf][0] = As[r * 36 + kk + tig];
                af[mf][1] = As[(r + 8) * 36 + kk + tig];
                af[mf][2] = As[r * 36 + kk + tig + 4];
                af[mf][3] = As[(r + 8) * 36 + kk + tig + 4];
            }
#pragma unroll
            for (int nf = 0; nf < 4; nf++) {
                int cn = wn + nf * 8 + gid;
                bf[nf][0] = Bs[(kk + tig) * 132 + cn];
                bf[nf][1] = Bs[(kk + tig + 4) * 132 + cn];
            }
#pragma unroll
            for (int mf = 0; mf < 4; mf++)
#pragma unroll
                for (int nf = 0; nf < 4; nf++)
                    mma_tf32(acc[mf][nf], af[mf], bf[nf]);
        }
        __syncthreads();
    }

    // ---- epilogue: + bias, store ----
#pragma unroll
    for (int mf = 0; mf < 4; mf++) {
        int row = m0 + wm + mf * 16 + gid;
#pragma unroll
        for (int nf = 0; nf < 4; nf++) {
            int col = n0 + wn + nf * 8 + tig * 2;
            float b0 = bias ? bias[col] : 0.f;
            float b1 = bias ? bias[col + 1] : 0.f;
            float2 v0 = make_float2(acc[mf][nf][0] + b0, acc[mf][nf][1] + b1);
            float2 v1 = make_float2(acc[mf][nf][2] + b0, acc[mf][nf][3] + b1);
            *reinterpret_cast<float2*>(C + (size_t)row * N + col)       = v0;
            *reinterpret_cast<float2*>(C + (size_t)(row + 8) * N + col) = v1;
        }
    }
}

// ---------------------------------------------------------------------------
// Persistent GRU recurrence. 128 blocks (co-resident: 1 block/SM at 179 KB
// smem), each owns 8 hidden units -> 24 gate columns of Wh held in smem for
// the whole kernel. Per step: h@Wh slice (fp32, K-split 8 across threads),
// gate nonlinearity, write h to double-buffered global, grid barrier, reload.
// ---------------------------------------------------------------------------
#define NBLK 128
#define NTHR 192
#define HS   1032   // padded stride for H=1024 rows in smem

__global__ __launch_bounds__(NTHR) void gru_recurrence(
    const float* __restrict__ enc, const float* __restrict__ Wh,
    const float* __restrict__ bhn, const float* __restrict__ xW)
{
    extern __shared__ float smem[];
    float* sh_h    = smem;                    // 16*HS
    float* sh_w    = sh_h + BATCH * HS;       // 24*HS
    float* sh_part = sh_w + 24 * HS;          // 384*8
    float* sh_gate = sh_part + 384 * 8;       // 384

    const int tid = threadIdx.x;
    const int j0  = blockIdx.x * 8;           // this block's hidden units
    const int kq  = tid & 7;                  // k slice: [kq*128, kq*128+128)
    const int cg  = (tid >> 3) % 6;           // col group: cols cg*4..+3 of 24
    const int bg  = tid / 48;                 // batch quad: bg*4..+3

    // Load Wh slice, transposed: sh_w[c][k] = Wh[k][g*HID + j0 + u], c=g*8+u
    for (int idx = tid; idx < 24 * HID; idx += NTHR) {
        int c = idx % 24, k = idx / 24;
        int g = c >> 3, u = c & 7;
        sh_w[c * HS + k] = Wh[(size_t)k * GATES + g * HID + j0 + u];
    }
    // h0 = encoder_state
    for (int idx = tid; idx < BATCH * HID; idx += NTHR)
        sh_h[(idx >> 10) * HS + (idx & 1023)] = enc[idx];
    __syncthreads();

    for (int t = 0; t < TLEN; t++) {
        // ---- partial dot products: 4 cols x 4 batches per thread ----
        float acc[4][4];
#pragma unroll
        for (int ci = 0; ci < 4; ci++)
#pragma unroll
            for (int bi = 0; bi < 4; bi++) acc[ci][bi] = 0.f;

        const int kbase = kq * 128;
        for (int k = 0; k < 128; k += 4) {
            float4 wv[4], hv[4];
#pragma unroll
            for (int ci = 0; ci < 4; ci++)
                wv[ci] = *reinterpret_cast<const float4*>(&sh_w[(cg * 4 + ci) * HS + kbase + k]);
#pragma unroll
            for (int bi = 0; bi < 4; bi++)
                hv[bi] = *reinterpret_cast<const float4*>(&sh_h[(bg * 4 + bi) * HS + kbase + k]);
#pragma unroll
            for (int ci = 0; ci < 4; ci++)
#pragma unroll
                for (int bi = 0; bi < 4; bi++)
                    acc[ci][bi] += wv[ci].x * hv[bi].x + wv[ci].y * hv[bi].y
                                 + wv[ci].z * hv[bi].z + wv[ci].w * hv[bi].w;
        }
#pragma unroll
        for (int ci = 0; ci < 4; ci++)
#pragma unroll
            for (int bi = 0; bi < 4; bi++)
                sh_part[((cg * 4 + ci) * 16 + bg * 4 + bi) * 8 + kq] = acc[ci][bi];
        __syncthreads();

        // ---- k-split reduction: 384 (c,b) sums ----
        for (int j = tid; j < 384; j += NTHR) {
            float s = 0.f;
#pragma unroll
            for (int q = 0; q < 8; q++) s += sh_part[j * 8 + q];
            sh_gate[j] = s;
        }
        __syncthreads();

        // ---- gates + state update: 16 batches x 8 units ----
        if (tid < 128) {
            int b = tid & 15, u = tid >> 4;
            int j = j0 + u;
            float hr = sh_gate[u * 16 + b];
            float hz = sh_gate[(8 + u) * 16 + b];
            float hn = sh_gate[(16 + u) * 16 + b];
            const float* xrow = xW + (size_t)(b * TLEN + t) * GATES;
            float xr = xrow[j], xz = xrow[HID + j], xn = xrow[2 * HID + j];
            float r  = 1.f / (1.f + expf(-(xr + hr)));
            float z  = 1.f / (1.f + expf(-(xz + hz)));
            float nn = tanhf(xn + r * (hn + bhn[j]));
            float hold = sh_h[b * HS + j];
            float hnew = (1.f - z) * nn + z * hold;
            g_hs[(size_t)(b * TLEN + t) * HID + j] = hnew;
            g_h[t & 1][b * HID + j] = hnew;
        }
        if (t == TLEN - 1) break;

        // ---- grid barrier (monotonic epoch; safe across graph replays) ----
        __threadfence();     // publish h stores device-wide
        __syncthreads();
        if (tid == 0) {
            unsigned epoch = g_bar_release;
            unsigned old = atomicAdd(&g_bar_count, 1);
            if (old == gridDim.x - 1) {
                g_bar_count = 0;
                __threadfence();
                g_bar_release = epoch + 1;
            } else {
                while (g_bar_release == epoch) { }
            }
        }
        __syncthreads();
        __threadfence();     // acquire (invalidates L1 so reloads see fresh h)

        // ---- reload full h ----
        const float4* src = reinterpret_cast<const float4*>(&g_h[t & 1][0]);
        for (int i = tid; i < BATCH * HID / 4; i += NTHR) {
            float4 v = __ldcg(&src[i]);
            int b = i >> 8, kk = (i & 255) << 2;
            *reinterpret_cast<float4*>(&sh_h[b * HS + kk]) = v;
        }
        __syncthreads();
    }
}

// ---------------------------------------------------------------------------
extern "C" void kernel_launch(void* const* d_in, const int* in_sizes, int n_in,
                              void* d_out, int out_size)
{
    const float *enc = nullptr, *embed = nullptr, *Wi = nullptr, *Wh = nullptr;
    const float *bi = nullptr, *bhn = nullptr, *Wo = nullptr, *bo = nullptr;
    const int* targets = nullptr;

    // All input element counts are distinct -> identify robustly by size.
    for (int i = 0; i < n_in; i++) {
        switch (in_sizes[i]) {
            case BATCH * HID:        enc     = (const float*)d_in[i]; break; // 16384
            case BATCH * TLEN:       targets = (const int*)  d_in[i]; break; // 4096
            case VOC * EMB:          embed   = (const float*)d_in[i]; break; // 16384000
            case EMB * GATES:        Wi      = (const float*)d_in[i]; break; // 1572864
            case HID * GATES:        Wh      = (const float*)d_in[i]; break; // 3145728
            case GATES:              bi      = (const float*)d_in[i]; break; // 3072
            case HID:                bhn     = (const float*)d_in[i]; break; // 1024
            case HID * VOC:          Wo      = (const float*)d_in[i]; break; // 32768000
            case VOC:                bo      = (const float*)d_in[i]; break; // 32000
            default: break;
        }
    }

    float *xW = nullptr, *hs = nullptr;
    cudaGetSymbolAddress((void**)&xW, g_xW);
    cudaGetSymbolAddress((void**)&hs, g_hs);

    // 1) xW = embed[targets] @ Wi + bi   (gather fused into A-tile load)
    gemm_tf32<<<dim3(GATES / 128, ROWS / 128), 256>>>(
        embed, targets, Wi, bi, xW, GATES, EMB, EMB);

    // 2) GRU recurrence (persistent, 128 co-resident blocks)
    const int smem_bytes = (BATCH * HS + 24 * HS + 384 * 8 + 384) * (int)sizeof(float);
    cudaFuncSetAttribute(gru_recurrence,
                         cudaFuncAttributeMaxDynamicSharedMemorySize, smem_bytes);
    gru_recurrence<<<NBLK, NTHR, smem_bytes>>>(enc, Wh, bhn, xW);

    // 3) logits = hs @ Wo + bo
    gemm_tf32<<<dim3(VOC / 128, ROWS / 128), 256>>>(
        hs, nullptr, Wo, bo, (float*)d_out, VOC, HID, HID);

    (void)out_size;
}

// round 4
// speedup vs baseline: 3.0221x; 3.0221x over previous
#include <cuda_runtime.h>
#include <cstdint>

#define BATCH 16
#define TLEN  256
#define HID   1024
#define EMB   512
#define VOC   32000
#define GATES 3072
#define ROWS  4096          // BATCH*TLEN

// ---------------- device scratch (no allocations allowed) ----------------
__device__ float g_xW[ROWS * GATES];        // 50.3 MB : x@Wi + bi (fp32)
__device__ float g_hst[ROWS * HID];         // 16.8 MB : hidden states, tf32-rounded
__device__ float g_h[2][BATCH * HID];       // double-buffered current h (fp32)
__device__ float g_xt[ROWS * EMB];          // 8.4 MB  : gathered embeddings, tf32
__device__ float g_wip[EMB * GATES];        // 6.3 MB  : Wi tf32
__device__ float g_wop[HID * VOC];          // 131 MB  : Wo tf32
__device__ uint4 g_whp[128 * 8 * 3 * 8 * 32]; // 12.6 MB: Wh packed mma fragments
__device__ unsigned g_bar_count = 0;
__device__ volatile unsigned g_bar_release = 0;  // monotonic epoch

// ---------------- helpers ----------------
__device__ __forceinline__ unsigned f2tf32(float f) {
    unsigned u;
    asm("cvt.rna.tf32.f32 %0, %1;" : "=r"(u) : "f"(f));
    return u;
}

__device__ __forceinline__ void mma_tf32(float c[4], const unsigned a[4],
                                         unsigned b0, unsigned b1) {
    asm volatile(
        "mma.sync.aligned.m16n8k8.row.col.f32.tf32.tf32.f32 "
        "{%0,%1,%2,%3}, {%4,%5,%6,%7}, {%8,%9}, {%0,%1,%2,%3};"
        : "+f"(c[0]), "+f"(c[1]), "+f"(c[2]), "+f"(c[3])
        : "r"(a[0]), "r"(a[1]), "r"(a[2]), "r"(a[3]), "r"(b0), "r"(b1));
}

__device__ __forceinline__ void cp16(uint32_t dst, const void* src) {
    asm volatile("cp.async.cg.shared.global [%0], [%1], 16;" :: "r"(dst), "l"(src));
}

// ---------------- prep kernels (run once per launch; cheap) ----------------
__global__ void cvt_tf32_k(const float4* __restrict__ in, float4* __restrict__ out, int n4) {
    int i = blockIdx.x * 256 + threadIdx.x;
    if (i >= n4) return;
    float4 v = in[i];
    v.x = __uint_as_float(f2tf32(v.x));
    v.y = __uint_as_float(f2tf32(v.y));
    v.z = __uint_as_float(f2tf32(v.z));
    v.w = __uint_as_float(f2tf32(v.w));
    out[i] = v;
}

__global__ void gather_x_k(const float4* __restrict__ embed, const int* __restrict__ targets,
                           float4* __restrict__ xt) {
    int i = blockIdx.x * 256 + threadIdx.x;     // ROWS*128 total
    int m = i >> 7, e = i & 127;
    int row = __ldg(targets + m);
    float4 v = embed[(size_t)row * 128 + e];
    v.x = __uint_as_float(f2tf32(v.x));
    v.y = __uint_as_float(f2tf32(v.y));
    v.z = __uint_as_float(f2tf32(v.z));
    v.w = __uint_as_float(f2tf32(v.w));
    xt[(size_t)m * 128 + e] = v;
}

// Pack Wh into mma B-fragment order:
// chunk c = ((((nb*8+kw)*3 + j)*8 + sp)*32 + lane); k = kw*128+sp*16, n = j*1024+nb*8+(lane>>2)
__global__ void pack_wh_k(const float* __restrict__ Wh, uint4* __restrict__ whp) {
    int c = blockIdx.x * 256 + threadIdx.x;     // 786432 chunks
    int lane = c & 31, t1 = c >> 5;
    int sp = t1 & 7; t1 >>= 3;
    int j = t1 % 3; t1 /= 3;
    int kw = t1 & 7, nb = t1 >> 3;
    int tig = lane & 3, gid = lane >> 2;
    int n  = j * 1024 + nb * 8 + gid;
    int kb = kw * 128 + sp * 16 + tig;
    uint4 v;
    v.x = f2tf32(Wh[(size_t)kb * GATES + n]);
    v.y = f2tf32(Wh[(size_t)(kb + 4) * GATES + n]);
    v.z = f2tf32(Wh[(size_t)(kb + 8) * GATES + n]);
    v.w = f2tf32(Wh[(size_t)(kb + 12) * GATES + n]);
    whp[c] = v;
}

// ---------------------------------------------------------------------------
// Pipelined tf32 GEMM (inputs already tf32 bits): C[M,N] = A[M,K]@B[K,N]+bias
// 128x128x32 tile, 256 thr, 3-stage cp.async, one __syncthreads per k-tile.
// grid = (M/128, N/128)  (M-major so consecutive blocks share the B tile)
// ---------------------------------------------------------------------------
#define ASZ 4608   // 128*36 words, 144B row pitch (16B aligned)
#define BSZ 4224   // 32*132 words, 528B row pitch (16B aligned)

__global__ __launch_bounds__(256) void gemm_pipe(
    const float* __restrict__ A, const float* __restrict__ B,
    const float* __restrict__ bias, float* __restrict__ C, int N, int K)
{
    extern __shared__ unsigned gsm[];
    unsigned* As = gsm;             // 3*ASZ
    unsigned* Bs = gsm + 3 * ASZ;   // 3*BSZ
    const uint32_t as_base = (uint32_t)__cvta_generic_to_shared(As);
    const uint32_t bs_base = (uint32_t)__cvta_generic_to_shared(Bs);

    const int t  = threadIdx.x;
    const int m0 = blockIdx.x * 128;
    const int n0 = blockIdx.y * 128;
    const int warp = t >> 5, lane = t & 31;
    const int gid = lane >> 2, tig = lane & 3;
    const int wm = (warp >> 2) * 64, wn = (warp & 3) * 32;

    const int ar  = t >> 3;        // 0..31
    const int ac  = (t & 7) * 4;
    const int bkr = t >> 5;        // 0..7
    const int bc  = (t & 31) * 4;

    const int NT = K / 32;

    float acc[4][4][4];
#pragma unroll
    for (int mf = 0; mf < 4; mf++)
#pragma unroll
        for (int nf = 0; nf < 4; nf++)
#pragma unroll
            for (int i = 0; i < 4; i++) acc[mf][nf][i] = 0.f;

    // prologue: stages 0,1
#pragma unroll
    for (int pre = 0; pre < 2; pre++) {
        int k0 = pre * 32;
#pragma unroll
        for (int p = 0; p < 4; p++) {
            int r = ar + 32 * p;
            cp16(as_base + (uint32_t)(pre * ASZ + r * 36 + ac) * 4,
                 A + (size_t)(m0 + r) * K + k0 + ac);
        }
#pragma unroll
        for (int p = 0; p < 4; p++) {
            int kr = bkr + 8 * p;
            cp16(bs_base + (uint32_t)(pre * BSZ + kr * 132 + bc) * 4,
                 B + (size_t)(k0 + kr) * N + n0 + bc);
        }
        asm volatile("cp.async.commit_group;");
    }

    for (int kt = 0; kt < NT; kt++) {
        asm volatile("cp.async.wait_group 1;");
        __syncthreads();

        // prefetch tile kt+2
        int ft = kt + 2;
        if (ft < NT) {
            int st = ft % 3, k0 = ft * 32;
#pragma unroll
            for (int p = 0; p < 4; p++) {
                int r = ar + 32 * p;
                cp16(as_base + (uint32_t)(st * ASZ + r * 36 + ac) * 4,
                     A + (size_t)(m0 + r) * K + k0 + ac);
            }
#pragma unroll
            for (int p = 0; p < 4; p++) {
                int kr = bkr + 8 * p;
                cp16(bs_base + (uint32_t)(st * BSZ + kr * 132 + bc) * 4,
                     B + (size_t)(k0 + kr) * N + n0 + bc);
            }
        }
        asm volatile("cp.async.commit_group;");

        const unsigned* Ab = As + (kt % 3) * ASZ;
        const unsigned* Bb = Bs + (kt % 3) * BSZ;
#pragma unroll
        for (int ks = 0; ks < 4; ks++) {
            const int kk = ks * 8;
            unsigned af[4][4], bf[4][2];
#pragma unroll
            for (int mf = 0; mf < 4; mf++) {
                int r = wm + mf * 16 + gid;
                af[mf][0] = Ab[r * 36 + kk + tig];
                af[mf][1] = Ab[(r + 8) * 36 + kk + tig];
                af[mf][2] = Ab[r * 36 + kk + tig + 4];
                af[mf][3] = Ab[(r + 8) * 36 + kk + tig + 4];
            }
#pragma unroll
            for (int nf = 0; nf < 4; nf++) {
                int cn = wn + nf * 8 + gid;
                bf[nf][0] = Bb[(kk + tig) * 132 + cn];
                bf[nf][1] = Bb[(kk + tig + 4) * 132 + cn];
            }
#pragma unroll
            for (int mf = 0; mf < 4; mf++)
#pragma unroll
                for (int nf = 0; nf < 4; nf++)
                    mma_tf32(acc[mf][nf], af[mf], bf[nf][0], bf[nf][1]);
        }
    }

#pragma unroll
    for (int mf = 0; mf < 4; mf++) {
        int row = m0 + wm + mf * 16 + gid;
#pragma unroll
        for (int nf = 0; nf < 4; nf++) {
            int col = n0 + wn + nf * 8 + tig * 2;
            float b0 = bias ? bias[col] : 0.f;
            float b1 = bias ? bias[col + 1] : 0.f;
            float2 v0 = make_float2(acc[mf][nf][0] + b0, acc[mf][nf][1] + b1);
            float2 v1 = make_float2(acc[mf][nf][2] + b0, acc[mf][nf][3] + b1);
            *reinterpret_cast<float2*>(C + (size_t)row * N + col)       = v0;
            *reinterpret_cast<float2*>(C + (size_t)(row + 8) * N + col) = v1;
        }
    }
}

// ---------------------------------------------------------------------------
// Tensor-core GRU recurrence. 128 persistent blocks x 256 thr (8 warps).
// Block owns 8 hidden units (3 gate n-tiles of 8 cols). Warp w owns K-slice
// [w*128, w*128+128). Packed Wh fragments live in smem for the whole kernel.
// Per step: 24 LDS.128 + 48 mma per thread, partial reduce, gate update,
// grid barrier, h all-gather + A-fragment rebuild.
// ---------------------------------------------------------------------------
#define RNB 128
#define RNT 256
#define HSH 1028                  // padded fp32 h stride (conflict-free frags)
#define WGT_WORDS (8*3*8*32*4)    // 24576 uints per block
#define PART_STRIDE 9

__global__ __launch_bounds__(RNT) void gru_rec(
    const float* __restrict__ enc, const uint4* __restrict__ whp,
    const float* __restrict__ bhn, const float* __restrict__ xW)
{
    extern __shared__ unsigned smu[];
    unsigned* sh_wgt = smu;                               // 24576
    float* sh_h      = (float*)(smu + WGT_WORDS);         // 16*HSH = 16448
    float* sh_part   = sh_h + BATCH * HSH;                // 384*9  = 3456

    const int tid  = threadIdx.x;
    const int warp = tid >> 5;
    const int lane = tid & 31;
    const int gid  = lane >> 2, tig = lane & 3;
    const int u0   = blockIdx.x * 8;

    // copy this block's packed weights into smem (stay for all 256 steps)
    {
        const uint4* src = whp + (size_t)blockIdx.x * (WGT_WORDS / 4);
        uint4* dst = (uint4*)sh_wgt;
        for (int i = tid; i < WGT_WORDS / 4; i += RNT) dst[i] = src[i];
    }
    // h0 = encoder_state
    for (int idx = tid; idx < BATCH * HID; idx += RNT)
        sh_h[(idx >> 10) * HSH + (idx & 1023)] = enc[idx];
    __syncthreads();

    // A fragments (registers), rebuilt every step
    unsigned a[16][4];
#pragma unroll
    for (int s = 0; s < 16; s++) {
        int k = warp * 128 + s * 8 + tig;
        a[s][0] = f2tf32(sh_h[gid * HSH + k]);
        a[s][1] = f2tf32(sh_h[(gid + 8) * HSH + k]);
        a[s][2] = f2tf32(sh_h[gid * HSH + k + 4]);
        a[s][3] = f2tf32(sh_h[(gid + 8) * HSH + k + 4]);
    }

    const uint4* wp = (const uint4*)sh_wgt + warp * (3 * 8 * 32);

    for (int t = 0; t < TLEN; t++) {
        // ---- mma: 3 gate n-tiles x 16 k-steps over this warp's K slice ----
        float c[3][4];
#pragma unroll
        for (int j = 0; j < 3; j++)
#pragma unroll
            for (int i = 0; i < 4; i++) c[j][i] = 0.f;

#pragma unroll
        for (int j = 0; j < 3; j++)
#pragma unroll
            for (int sp = 0; sp < 8; sp++) {
                uint4 bv = wp[(j * 8 + sp) * 32 + lane];
                mma_tf32(c[j], a[2 * sp],     bv.x, bv.y);
                mma_tf32(c[j], a[2 * sp + 1], bv.z, bv.w);
            }

        // ---- stash partials: (gate j, batch row, unit col) x 8 warps ----
#pragma unroll
        for (int j = 0; j < 3; j++) {
            sh_part[((j * 16 + gid) * 8 + tig * 2)     * PART_STRIDE + warp] = c[j][0];
            sh_part[((j * 16 + gid) * 8 + tig * 2 + 1) * PART_STRIDE + warp] = c[j][1];
            sh_part[((j * 16 + gid + 8) * 8 + tig * 2)     * PART_STRIDE + warp] = c[j][2];
            sh_part[((j * 16 + gid + 8) * 8 + tig * 2 + 1) * PART_STRIDE + warp] = c[j][3];
        }
        __syncthreads();

        // ---- reduce 8 warps + gate update: thread (b,u), 128 active ----
        if (tid < 128) {
            int b = tid >> 3, u = tid & 7;
            float hr = 0.f, hz = 0.f, hn = 0.f;
#pragma unroll
            for (int q = 0; q < 8; q++) {
                hr += sh_part[((0 * 16 + b) * 8 + u) * PART_STRIDE + q];
                hz += sh_part[((1 * 16 + b) * 8 + u) * PART_STRIDE + q];
                hn += sh_part[((2 * 16 + b) * 8 + u) * PART_STRIDE + q];
            }
            int j = u0 + u;
            const float* xrow = xW + (size_t)(b * TLEN + t) * GATES;
            float xr = xrow[j], xz = xrow[HID + j], xn = xrow[2 * HID + j];
            float r  = 1.f / (1.f + expf(-(xr + hr)));
            float z  = 1.f / (1.f + expf(-(xz + hz)));
            float nn = tanhf(xn + r * (hn + bhn[j]));
            float hold = sh_h[b * HSH + j];
            float hnew = (1.f - z) * nn + z * hold;
            g_hst[(size_t)(b * TLEN + t) * HID + j] = __uint_as_float(f2tf32(hnew));
            g_h[t & 1][b * HID + j] = hnew;
        }
        if (t == TLEN - 1) break;

        // ---- grid barrier (monotonic epoch) ----
        __threadfence();
        __syncthreads();
        if (tid == 0) {
            unsigned epoch = g_bar_release;
            unsigned old = atomicAdd(&g_bar_count, 1);
            if (old == gridDim.x - 1) {
                g_bar_count = 0;
                __threadfence();
                g_bar_release = epoch + 1;
            } else {
                while (g_bar_release == epoch) { }
            }
        }
        __syncthreads();
        __threadfence();

        // ---- all-gather h, rebuild A fragments ----
        const float4* src = reinterpret_cast<const float4*>(&g_h[t & 1][0]);
        for (int i = tid; i < BATCH * HID / 4; i += RNT) {
            float4 v = __ldcg(&src[i]);
            int b = i >> 8, kk = (i & 255) << 2;
            *reinterpret_cast<float4*>(&sh_h[b * HSH + kk]) = v;
        }
        __syncthreads();
#pragma unroll
        for (int s = 0; s < 16; s++) {
            int k = warp * 128 + s * 8 + tig;
            a[s][0] = f2tf32(sh_h[gid * HSH + k]);
            a[s][1] = f2tf32(sh_h[(gid + 8) * HSH + k]);
            a[s][2] = f2tf32(sh_h[gid * HSH + k + 4]);
            a[s][3] = f2tf32(sh_h[(gid + 8) * HSH + k + 4]);
        }
    }
}

// ---------------------------------------------------------------------------
extern "C" void kernel_launch(void* const* d_in, const int* in_sizes, int n_in,
                              void* d_out, int out_size)
{
    const float *enc = nullptr, *embed = nullptr, *Wi = nullptr, *Wh = nullptr;
    const float *bi = nullptr, *bhn = nullptr, *Wo = nullptr, *bo = nullptr;
    const int* targets = nullptr;

    for (int i = 0; i < n_in; i++) {
        switch (in_sizes[i]) {
            case BATCH * HID:  enc     = (const float*)d_in[i]; break;
            case BATCH * TLEN: targets = (const int*)  d_in[i]; break;
            case VOC * EMB:    embed   = (const float*)d_in[i]; break;
            case EMB * GATES:  Wi      = (const float*)d_in[i]; break;
            case HID * GATES:  Wh      = (const float*)d_in[i]; break;
            case GATES:        bi      = (const float*)d_in[i]; break;
            case HID:          bhn     = (const float*)d_in[i]; break;
            case HID * VOC:    Wo      = (const float*)d_in[i]; break;
            case VOC:          bo      = (const float*)d_in[i]; break;
            default: break;
        }
    }

    float *xW, *hst, *xt, *wip, *wop;
    uint4* whp;
    cudaGetSymbolAddress((void**)&xW,  g_xW);
    cudaGetSymbolAddress((void**)&hst, g_hst);
    cudaGetSymbolAddress((void**)&xt,  g_xt);
    cudaGetSymbolAddress((void**)&wip, g_wip);
    cudaGetSymbolAddress((void**)&wop, g_wop);
    cudaGetSymbolAddress((void**)&whp, g_whp);

    static bool attr_done = false;
    const int gemm_smem = 3 * (ASZ + BSZ) * 4;   // 105984
    const int rec_smem  = (WGT_WORDS + BATCH * HSH + 384 * PART_STRIDE) * 4;
    if (!attr_done) {
        cudaFuncSetAttribute(gemm_pipe, cudaFuncAttributeMaxDynamicSharedMemorySize, gemm_smem);
        cudaFuncSetAttribute(gru_rec,   cudaFuncAttributeMaxDynamicSharedMemorySize, rec_smem);
        attr_done = true;
    }

    // ---- prep (once per replay; ~70us total) ----
    cvt_tf32_k<<<(EMB * GATES / 4 + 255) / 256, 256>>>((const float4*)Wi, (float4*)wip, EMB * GATES / 4);
    cvt_tf32_k<<<(HID * VOC / 4 + 255) / 256, 256>>>((const float4*)Wo, (float4*)wop, HID * VOC / 4);
    pack_wh_k<<<(128 * 8 * 3 * 8 * 32) / 256, 256>>>(Wh, whp);
    gather_x_k<<<ROWS * 128 / 256, 256>>>((const float4*)embed, targets, (float4*)xt);

    // ---- 1) xW = x @ Wi + bi ----
    gemm_pipe<<<dim3(ROWS / 128, GATES / 128), 256, gemm_smem>>>(xt, wip, bi, xW, GATES, EMB);

    // ---- 2) GRU recurrence ----
    gru_rec<<<RNB, RNT, rec_smem>>>(enc, whp, bhn, xW);

    // ---- 3) logits = hs @ Wo + bo ----
    gemm_pipe<<<dim3(ROWS / 128, VOC / 128), 256, gemm_smem>>>(hst, wop, bo, (float*)d_out, VOC, HID);

    (void)out_size;
}